// round 1
// baseline (speedup 1.0000x reference)
#include <cuda_runtime.h>
#include <math.h>

#define N_NODES   100000
#define N_EDGES   1600000
#define N_GRAPHS  1024
#define HDIM      64
#define EPSV      1e-7f
#define SHIFT     40.0f

// ---------------- scratch (static device globals; no allocation) -------------
__device__ float g_h0[N_NODES * HDIM];
__device__ float g_h1[N_NODES * HDIM];
__device__ float g_denom[N_NODES * HDIM];
__device__ float g_numer[N_NODES * HDIM];
__device__ float g_pool[N_GRAPHS * HDIM];
__device__ float g_cnt[N_GRAPHS];

__device__ __forceinline__ void red4(float* p, float a, float b, float c, float d) {
    asm volatile("red.global.add.v4.f32 [%0], {%1,%2,%3,%4};"
                 :: "l"(p), "f"(a), "f"(b), "f"(c), "f"(d) : "memory");
}

// ---------------- zero scratch ------------------------------------------------
__global__ void __launch_bounds__(256) zero_kernel() {
    int i = blockIdx.x * 256 + threadIdx.x;
    if (i < N_NODES * HDIM) { g_denom[i] = 0.0f; g_numer[i] = 0.0f; }
    if (i < N_GRAPHS * HDIM) g_pool[i] = 0.0f;
    if (i < N_GRAPHS) g_cnt[i] = 0.0f;
}

// ---------------- h0 = x @ node_W + node_b  (16 -> 64) ------------------------
__global__ void __launch_bounds__(256) input_proj(const float* __restrict__ x,
                                                  const float* __restrict__ W,
                                                  const float* __restrict__ b) {
    __shared__ float4 sW[256];   // [16 k][16 f4]
    __shared__ float4 sb[16];
    int tid = threadIdx.x;
    sW[tid] = ((const float4*)W)[tid];
    if (tid < 16) sb[tid] = ((const float4*)b)[tid];
    __syncthreads();

    int t = blockIdx.x * 256 + tid;
    int n = t >> 4, g = t & 15;
    if (n >= N_NODES) return;
    const float4* xr = (const float4*)(x + n * 16);
    float4 x0 = xr[0], x1 = xr[1], x2 = xr[2], x3 = xr[3];
    float4 acc = sb[g];
#define ISTEP(av, kk) { float4 w = sW[(kk)*16 + g]; \
    acc.x = fmaf(av, w.x, acc.x); acc.y = fmaf(av, w.y, acc.y); \
    acc.z = fmaf(av, w.z, acc.z); acc.w = fmaf(av, w.w, acc.w); }
    ISTEP(x0.x, 0)  ISTEP(x0.y, 1)  ISTEP(x0.z, 2)  ISTEP(x0.w, 3)
    ISTEP(x1.x, 4)  ISTEP(x1.y, 5)  ISTEP(x1.z, 6)  ISTEP(x1.w, 7)
    ISTEP(x2.x, 8)  ISTEP(x2.y, 9)  ISTEP(x2.z, 10) ISTEP(x2.w, 11)
    ISTEP(x3.x, 12) ISTEP(x3.y, 13) ISTEP(x3.z, 14) ISTEP(x3.w, 15)
#undef ISTEP
    ((float4*)(g_h0 + n * HDIM))[g] = acc;
}

// ---------------- edge pass: accumulate denom/numer of shifted softmax --------
// 16 threads per edge, 4 features each. One pass per conv (max pass eliminated
// by shift-invariance of softmax: subtract fixed SHIFT instead of per-dst max).
__global__ void __launch_bounds__(256) edge_pass(int cur,
                                                 const float* __restrict__ edge_attr,
                                                 const int* __restrict__ esrc,
                                                 const int* __restrict__ edst,
                                                 const float* __restrict__ eW,
                                                 const float* __restrict__ eb) {
    __shared__ float4 sW[128];  // [8 k][16 f4]
    __shared__ float4 sb[16];
    int tid = threadIdx.x;
    if (tid < 128) sW[tid] = ((const float4*)eW)[tid];
    if (tid < 16)  sb[tid] = ((const float4*)eb)[tid];
    __syncthreads();

    const float* h = cur ? g_h1 : g_h0;
    int e   = blockIdx.x * 16 + (tid >> 4);   // N_EDGES/16 = 100000 blocks, exact
    int sub = tid & 15;
    int s = __ldg(esrc + e);
    int d = __ldg(edst + e);
    const float4* ar = (const float4*)(edge_attr + (size_t)e * 8);
    float4 a0 = __ldg(ar), a1 = __ldg(ar + 1);
    float4 hv = *(const float4*)(h + (size_t)s * HDIM + sub * 4);
    float4 acc = sb[sub];
#define ESTEP(av, kk) { float4 w = sW[(kk)*16 + sub]; \
    acc.x = fmaf(av, w.x, acc.x); acc.y = fmaf(av, w.y, acc.y); \
    acc.z = fmaf(av, w.z, acc.z); acc.w = fmaf(av, w.w, acc.w); }
    ESTEP(a0.x, 0) ESTEP(a0.y, 1) ESTEP(a0.z, 2) ESTEP(a0.w, 3)
    ESTEP(a1.x, 4) ESTEP(a1.y, 5) ESTEP(a1.z, 6) ESTEP(a1.w, 7)
#undef ESTEP
    float m0 = fmaxf(hv.x + acc.x, 0.0f) + EPSV;
    float m1 = fmaxf(hv.y + acc.y, 0.0f) + EPSV;
    float m2 = fmaxf(hv.z + acc.z, 0.0f) + EPSV;
    float m3 = fmaxf(hv.w + acc.w, 0.0f) + EPSV;
    float e0 = __expf(m0 - SHIFT);
    float e1 = __expf(m1 - SHIFT);
    float e2 = __expf(m2 - SHIFT);
    float e3 = __expf(m3 - SHIFT);
    size_t off = (size_t)d * HDIM + sub * 4;
    red4(g_denom + off, e0, e1, e2, e3);
    red4(g_numer + off, m0 * e0, m1 * e1, m2 * e2, m3 * e3);
}

// ---------------- node update: out = h + numer/denom; MLP 64->128->64; relu ---
// Thread-per-node; W1/W2/biases in shared (broadcast reads). Also re-zeroes
// denom/numer for the next conv.
__global__ void __launch_bounds__(128) node_mlp(int cur,
                                                const float* __restrict__ W1,
                                                const float* __restrict__ b1,
                                                const float* __restrict__ W2,
                                                const float* __restrict__ b2) {
    extern __shared__ float4 s4[];
    // layout (float4 units): sW1 [0,2048), sW2 [2048,4096), sb1 [4096,4128), sb2 [4128,4144)
    int tid = threadIdx.x;
    const float4* W1_4 = (const float4*)W1;
    const float4* W2_4 = (const float4*)W2;
#pragma unroll
    for (int i = 0; i < 16; i++) s4[tid + i * 128] = W1_4[tid + i * 128];
#pragma unroll
    for (int i = 0; i < 16; i++) s4[2048 + tid + i * 128] = W2_4[tid + i * 128];
    if (tid < 32) s4[4096 + tid] = ((const float4*)b1)[tid];
    if (tid < 16) s4[4128 + tid] = ((const float4*)b2)[tid];
    __syncthreads();
    const float4* sW1 = s4;
    const float4* sW2 = s4 + 2048;
    const float4* sb1 = s4 + 4096;
    const float4* sb2 = s4 + 4128;

    int n = blockIdx.x * 128 + tid;
    if (n >= N_NODES) return;
    const float* h_in = cur ? g_h1 : g_h0;
    float*       h_out = cur ? g_h0 : g_h1;

    float x[64];
    {
        const float4* hr = (const float4*)(h_in + (size_t)n * HDIM);
        float4* dz = (float4*)(g_denom + (size_t)n * HDIM);
        float4* nz = (float4*)(g_numer + (size_t)n * HDIM);
        float4 zer = make_float4(0.f, 0.f, 0.f, 0.f);
#pragma unroll
        for (int k4 = 0; k4 < 16; k4++) {
            float4 hv = hr[k4], dv = dz[k4], nv = nz[k4];
            x[k4 * 4 + 0] = hv.x + nv.x / fmaxf(dv.x, 1e-16f);
            x[k4 * 4 + 1] = hv.y + nv.y / fmaxf(dv.y, 1e-16f);
            x[k4 * 4 + 2] = hv.z + nv.z / fmaxf(dv.z, 1e-16f);
            x[k4 * 4 + 3] = hv.w + nv.w / fmaxf(dv.w, 1e-16f);
            dz[k4] = zer; nz[k4] = zer;   // re-zero for next conv
        }
    }

    float acc2[64];
#pragma unroll
    for (int f4 = 0; f4 < 16; f4++) {
        float4 bv = sb2[f4];
        acc2[f4 * 4 + 0] = bv.x; acc2[f4 * 4 + 1] = bv.y;
        acc2[f4 * 4 + 2] = bv.z; acc2[f4 * 4 + 3] = bv.w;
    }

    for (int jc = 0; jc < 32; jc++) {       // dynamic: keeps code size small
        float4 bv = sb1[jc];
        float h0 = bv.x, h1 = bv.y, h2 = bv.z, h3 = bv.w;
#pragma unroll
        for (int k = 0; k < 64; k++) {
            float4 w = sW1[k * 32 + jc];
            float xv = x[k];
            h0 = fmaf(xv, w.x, h0); h1 = fmaf(xv, w.y, h1);
            h2 = fmaf(xv, w.z, h2); h3 = fmaf(xv, w.w, h3);
        }
        h0 = fmaxf(h0, 0.f); h1 = fmaxf(h1, 0.f);
        h2 = fmaxf(h2, 0.f); h3 = fmaxf(h3, 0.f);
#pragma unroll
        for (int f4 = 0; f4 < 16; f4++) {
            float4 w0 = sW2[(jc * 4 + 0) * 16 + f4];
            float4 w1 = sW2[(jc * 4 + 1) * 16 + f4];
            float4 w2 = sW2[(jc * 4 + 2) * 16 + f4];
            float4 w3 = sW2[(jc * 4 + 3) * 16 + f4];
            acc2[f4 * 4 + 0] += h0 * w0.x + h1 * w1.x + h2 * w2.x + h3 * w3.x;
            acc2[f4 * 4 + 1] += h0 * w0.y + h1 * w1.y + h2 * w2.y + h3 * w3.y;
            acc2[f4 * 4 + 2] += h0 * w0.z + h1 * w1.z + h2 * w2.z + h3 * w3.z;
            acc2[f4 * 4 + 3] += h0 * w0.w + h1 * w1.w + h2 * w2.w + h3 * w3.w;
        }
    }

    float4* orow = (float4*)(h_out + (size_t)n * HDIM);
#pragma unroll
    for (int f4 = 0; f4 < 16; f4++)
        orow[f4] = make_float4(fmaxf(acc2[f4 * 4 + 0], 0.f), fmaxf(acc2[f4 * 4 + 1], 0.f),
                               fmaxf(acc2[f4 * 4 + 2], 0.f), fmaxf(acc2[f4 * 4 + 3], 0.f));
}

// ---------------- global mean pool (accumulate) -------------------------------
__global__ void __launch_bounds__(256) pool_kernel(int cur, const int* __restrict__ batch) {
    int t = blockIdx.x * 256 + threadIdx.x;
    int n = t >> 4, g = t & 15;
    if (n >= N_NODES) return;
    const float* h = cur ? g_h1 : g_h0;
    int b = __ldg(batch + n);
    float4 hv = ((const float4*)(h + (size_t)n * HDIM))[g];
    red4(g_pool + (size_t)b * HDIM + g * 4, hv.x, hv.y, hv.z, hv.w);
    if (g == 0) atomicAdd(g_cnt + b, 1.0f);
}

// ---------------- graph head: concat -> 74x32 -> 32x32 -> 32x1 -> sigmoid -----
__global__ void __launch_bounds__(256) head_kernel(const float* __restrict__ graph_attr,
                                                   const float* __restrict__ d1W, const float* __restrict__ d1b,
                                                   const float* __restrict__ d2W, const float* __restrict__ d2b,
                                                   const float* __restrict__ oW,  const float* __restrict__ ob,
                                                   float* __restrict__ out) {
    int t = blockIdx.x * 256 + threadIdx.x;
    int g = t >> 5, lane = t & 31;
    if (g >= N_GRAPHS) return;
    float cnt = fmaxf(g_cnt[g], 1.0f);
    float p0 = g_pool[g * HDIM + lane] / cnt;
    float p1 = g_pool[g * HDIM + 32 + lane] / cnt;
    float ga = (lane < 10) ? graph_attr[g * 10 + lane] : 0.0f;

    float a = d1b[lane];
#pragma unroll
    for (int k = 0; k < 32; k++) a = fmaf(__shfl_sync(0xffffffffu, p0, k), d1W[k * 32 + lane], a);
#pragma unroll
    for (int k = 0; k < 32; k++) a = fmaf(__shfl_sync(0xffffffffu, p1, k), d1W[(32 + k) * 32 + lane], a);
#pragma unroll
    for (int k = 0; k < 10; k++) a = fmaf(__shfl_sync(0xffffffffu, ga, k), d1W[(64 + k) * 32 + lane], a);
    a = fmaxf(a, 0.0f);

    float bsum = d2b[lane];
#pragma unroll
    for (int k = 0; k < 32; k++) bsum = fmaf(__shfl_sync(0xffffffffu, a, k), d2W[k * 32 + lane], bsum);
    bsum = fmaxf(bsum, 0.0f);

    float v = bsum * oW[lane];
#pragma unroll
    for (int s = 16; s > 0; s >>= 1) v += __shfl_xor_sync(0xffffffffu, v, s);
    if (lane == 0) out[g] = 1.0f / (1.0f + expf(-(v + ob[0])));
}

// ---------------- launch -------------------------------------------------------
extern "C" void kernel_launch(void* const* d_in, const int* in_sizes, int n_in,
                              void* d_out, int out_size) {
    // metadata order = setup_inputs dict order
    const float* x          = (const float*)d_in[0];
    const float* edge_attr  = (const float*)d_in[1];
    const float* graph_attr = (const float*)d_in[2];
    const int*   edge_index = (const int*)d_in[3];
    const int*   batch      = (const int*)d_in[4];
    const float* node_W     = (const float*)d_in[5];
    const float* node_b     = (const float*)d_in[6];
    const float* edge_W     = (const float*)d_in[7];
    const float* edge_b     = (const float*)d_in[8];
    const float* cW1[3] = { (const float*)d_in[9],  (const float*)d_in[13], (const float*)d_in[17] };
    const float* cb1[3] = { (const float*)d_in[10], (const float*)d_in[14], (const float*)d_in[18] };
    const float* cW2[3] = { (const float*)d_in[11], (const float*)d_in[15], (const float*)d_in[19] };
    const float* cb2[3] = { (const float*)d_in[12], (const float*)d_in[16], (const float*)d_in[20] };
    const float* d1W = (const float*)d_in[21];
    const float* d1b = (const float*)d_in[22];
    const float* d2W = (const float*)d_in[23];
    const float* d2b = (const float*)d_in[24];
    const float* oW  = (const float*)d_in[25];
    const float* ob  = (const float*)d_in[26];
    const int* esrc = edge_index;
    const int* edst = edge_index + N_EDGES;
    float* out = (float*)d_out;

    const int SMEM_MLP = 4144 * 16;  // 66304 bytes
    cudaFuncSetAttribute((const void*)node_mlp,
                         cudaFuncAttributeMaxDynamicSharedMemorySize, SMEM_MLP);

    zero_kernel<<<(N_NODES * HDIM + 255) / 256, 256>>>();
    input_proj<<<(N_NODES * 16) / 256, 256>>>(x, node_W, node_b);

    int cur = 0;
    for (int c = 0; c < 3; c++) {
        edge_pass<<<N_EDGES / 16, 256>>>(cur, edge_attr, esrc, edst, edge_W, edge_b);
        node_mlp<<<(N_NODES + 127) / 128, 128, SMEM_MLP>>>(cur, cW1[c], cb1[c], cW2[c], cb2[c]);
        cur ^= 1;
    }

    pool_kernel<<<(N_NODES * 16) / 256 + 1, 256>>>(cur, batch);
    head_kernel<<<(N_GRAPHS * 32) / 256, 256>>>(graph_attr, d1W, d1b, d2W, d2b, oW, ob, out);
}

// round 2
// speedup vs baseline: 1.3111x; 1.3111x over previous
#include <cuda_runtime.h>
#include <math.h>

#define N_NODES   100000
#define N_EDGES   1600000
#define N_GRAPHS  1024
#define HDIM      64
#define EPSV      1e-7f
#define SHIFT     40.0f
#define SCAN_BLK  512
#define NSCAN     ((N_NODES + SCAN_BLK - 1) / SCAN_BLK)   // 196

// ---------------- scratch (static device globals; no allocation) -------------
__device__ float g_h0[N_NODES * HDIM];
__device__ float g_h1[N_NODES * HDIM];
__device__ float g_agg[N_NODES * HDIM];
__device__ float g_pool[N_GRAPHS * HDIM];
__device__ float g_cnt[N_GRAPHS];
// CSR
__device__ int   g_deg[N_NODES];
__device__ int   g_off[N_NODES];
__device__ int   g_cursor[N_NODES];
__device__ int   g_bsum[NSCAN];
__device__ int   g_src_s[N_EDGES];
__device__ float g_ea_s[(size_t)N_EDGES * 8];

__device__ __forceinline__ void red4(float* p, float a, float b, float c, float d) {
    asm volatile("red.global.add.v4.f32 [%0], {%1,%2,%3,%4};"
                 :: "l"(p), "f"(a), "f"(b), "f"(c), "f"(d) : "memory");
}

// ---------------- zero small scratch ------------------------------------------
__global__ void __launch_bounds__(256) zero_small() {
    int i = blockIdx.x * 256 + threadIdx.x;
    if (i < N_NODES) g_deg[i] = 0;
    if (i < N_GRAPHS * HDIM) g_pool[i] = 0.0f;
    if (i < N_GRAPHS) g_cnt[i] = 0.0f;
}

// ---------------- h0 = x @ node_W + node_b  (16 -> 64) ------------------------
__global__ void __launch_bounds__(256) input_proj(const float* __restrict__ x,
                                                  const float* __restrict__ W,
                                                  const float* __restrict__ b) {
    __shared__ float4 sW[256];
    __shared__ float4 sb[16];
    int tid = threadIdx.x;
    sW[tid] = ((const float4*)W)[tid];
    if (tid < 16) sb[tid] = ((const float4*)b)[tid];
    __syncthreads();

    int t = blockIdx.x * 256 + tid;
    int n = t >> 4, g = t & 15;
    if (n >= N_NODES) return;
    const float4* xr = (const float4*)(x + n * 16);
    float4 x0 = xr[0], x1 = xr[1], x2 = xr[2], x3 = xr[3];
    float4 acc = sb[g];
#define ISTEP(av, kk) { float4 w = sW[(kk)*16 + g]; \
    acc.x = fmaf(av, w.x, acc.x); acc.y = fmaf(av, w.y, acc.y); \
    acc.z = fmaf(av, w.z, acc.z); acc.w = fmaf(av, w.w, acc.w); }
    ISTEP(x0.x, 0)  ISTEP(x0.y, 1)  ISTEP(x0.z, 2)  ISTEP(x0.w, 3)
    ISTEP(x1.x, 4)  ISTEP(x1.y, 5)  ISTEP(x1.z, 6)  ISTEP(x1.w, 7)
    ISTEP(x2.x, 8)  ISTEP(x2.y, 9)  ISTEP(x2.z, 10) ISTEP(x2.w, 11)
    ISTEP(x3.x, 12) ISTEP(x3.y, 13) ISTEP(x3.z, 14) ISTEP(x3.w, 15)
#undef ISTEP
    ((float4*)(g_h0 + (size_t)n * HDIM))[g] = acc;
}

// ---------------- CSR build: histogram, scan, scatter --------------------------
__global__ void __launch_bounds__(256) hist_kernel(const int* __restrict__ edst) {
    int e = blockIdx.x * 256 + threadIdx.x;
    if (e < N_EDGES) atomicAdd(&g_deg[edst[e]], 1);
}

__global__ void __launch_bounds__(SCAN_BLK) scan1_kernel() {
    __shared__ int wsum[SCAN_BLK / 32];
    int d = blockIdx.x * SCAN_BLK + threadIdx.x;
    int v = (d < N_NODES) ? g_deg[d] : 0;
    int lane = threadIdx.x & 31, w = threadIdx.x >> 5;
    int inc = v;
#pragma unroll
    for (int o = 1; o < 32; o <<= 1) {
        int t = __shfl_up_sync(0xffffffffu, inc, o);
        if (lane >= o) inc += t;
    }
    if (lane == 31) wsum[w] = inc;
    __syncthreads();
    if (w == 0) {
        int s = (lane < SCAN_BLK / 32) ? wsum[lane] : 0;
#pragma unroll
        for (int o = 1; o < 16; o <<= 1) {
            int t = __shfl_up_sync(0xffffffffu, s, o);
            if (lane >= o) s += t;
        }
        if (lane < SCAN_BLK / 32) wsum[lane] = s;
    }
    __syncthreads();
    int base = (w > 0) ? wsum[w - 1] : 0;
    if (d < N_NODES) g_off[d] = base + inc - v;
    if (threadIdx.x == SCAN_BLK - 1) g_bsum[blockIdx.x] = base + inc;
}

__global__ void __launch_bounds__(256) scan2_kernel() {
    __shared__ int wsum[8];
    int i = threadIdx.x;
    int v = (i < NSCAN) ? g_bsum[i] : 0;
    int lane = i & 31, w = i >> 5;
    int inc = v;
#pragma unroll
    for (int o = 1; o < 32; o <<= 1) {
        int t = __shfl_up_sync(0xffffffffu, inc, o);
        if (lane >= o) inc += t;
    }
    if (lane == 31) wsum[w] = inc;
    __syncthreads();
    if (w == 0 && lane < 8) {
        int s = wsum[lane];
#pragma unroll
        for (int o = 1; o < 8; o <<= 1) {
            int t = __shfl_up_sync(0x000000ffu, s, o);
            if (lane >= o) s += t;
        }
        wsum[lane] = s;
    }
    __syncthreads();
    int base = (w > 0) ? wsum[w - 1] : 0;
    if (i < NSCAN) g_bsum[i] = base + inc - v;
}

__global__ void __launch_bounds__(256) scan3_kernel() {
    int d = blockIdx.x * 256 + threadIdx.x;
    if (d < N_NODES) {
        int o = g_off[d] + g_bsum[d / SCAN_BLK];
        g_off[d] = o;
        g_cursor[d] = o;
    }
}

__global__ void __launch_bounds__(256) scatter_kernel(const float* __restrict__ edge_attr,
                                                      const int* __restrict__ esrc,
                                                      const int* __restrict__ edst) {
    int e = blockIdx.x * 256 + threadIdx.x;
    if (e >= N_EDGES) return;
    int d = edst[e];
    int pos = atomicAdd(&g_cursor[d], 1);
    const float4* a = (const float4*)(edge_attr + (size_t)e * 8);
    float4 a0 = __ldg(a), a1 = __ldg(a + 1);
    g_src_s[pos] = esrc[e];
    float4* o = (float4*)(g_ea_s + (size_t)pos * 8);
    o[0] = a0; o[1] = a1;
}

// ---------------- per-dst aggregation (warp per dst, no atomics) ---------------
__global__ void __launch_bounds__(256) agg_pass(int cur,
                                                const float* __restrict__ eW,
                                                const float* __restrict__ eb) {
    int lane = threadIdx.x & 31;
    int d = blockIdx.x * 8 + (threadIdx.x >> 5);   // grid 12500 exact
    const float* h = cur ? g_h1 : g_h0;

    // edge-W slice for this lane's 2 features, in registers
    float2 w0 = ((const float2*)(eW + 0 * 64))[lane];
    float2 w1 = ((const float2*)(eW + 1 * 64))[lane];
    float2 w2 = ((const float2*)(eW + 2 * 64))[lane];
    float2 w3 = ((const float2*)(eW + 3 * 64))[lane];
    float2 w4 = ((const float2*)(eW + 4 * 64))[lane];
    float2 w5 = ((const float2*)(eW + 5 * 64))[lane];
    float2 w6 = ((const float2*)(eW + 6 * 64))[lane];
    float2 w7 = ((const float2*)(eW + 7 * 64))[lane];
    float2 bb = ((const float2*)eb)[lane];

    int start = g_off[d];
    int cnt = g_deg[d];
    float den0 = 0.f, den1 = 0.f, num0 = 0.f, num1 = 0.f;

    for (int i = start; i < start + cnt; i++) {
        int s = __ldg(g_src_s + i);
        const float4* ap = (const float4*)(g_ea_s + (size_t)i * 8);
        float4 a0 = __ldg(ap), a1 = __ldg(ap + 1);
        float2 hv = *(const float2*)(h + (size_t)s * HDIM + 2 * lane);
        float e0 = bb.x, e1 = bb.y;
        e0 = fmaf(a0.x, w0.x, e0); e1 = fmaf(a0.x, w0.y, e1);
        e0 = fmaf(a0.y, w1.x, e0); e1 = fmaf(a0.y, w1.y, e1);
        e0 = fmaf(a0.z, w2.x, e0); e1 = fmaf(a0.z, w2.y, e1);
        e0 = fmaf(a0.w, w3.x, e0); e1 = fmaf(a0.w, w3.y, e1);
        e0 = fmaf(a1.x, w4.x, e0); e1 = fmaf(a1.x, w4.y, e1);
        e0 = fmaf(a1.y, w5.x, e0); e1 = fmaf(a1.y, w5.y, e1);
        e0 = fmaf(a1.z, w6.x, e0); e1 = fmaf(a1.z, w6.y, e1);
        e0 = fmaf(a1.w, w7.x, e0); e1 = fmaf(a1.w, w7.y, e1);
        float m0 = fmaxf(hv.x + e0, 0.0f) + EPSV;
        float m1 = fmaxf(hv.y + e1, 0.0f) + EPSV;
        float x0 = __expf(m0 - SHIFT);
        float x1 = __expf(m1 - SHIFT);
        den0 += x0; den1 += x1;
        num0 = fmaf(m0, x0, num0);
        num1 = fmaf(m1, x1, num1);
    }

    float2 out;
    out.x = num0 / fmaxf(den0, 1e-16f);
    out.y = num1 / fmaxf(den1, 1e-16f);
    *(float2*)(g_agg + (size_t)d * HDIM + 2 * lane) = out;
}

// ---------------- node MLP: smem-tiled GEMM (64 nodes / block) -----------------
// smem (floats): sH[128*68=8704] | union{ sX[64*68=4352] + sW1[8192] , sW2[8192] }
#define SX_STRIDE 68
#define SH_STRIDE 68
#define SMEM_FLOATS (8704 + 4352 + 8192)   // 21248 -> 84992 bytes

__global__ void __launch_bounds__(256, 2) node_mlp(int cur,
                                                   const float* __restrict__ W1,
                                                   const float* __restrict__ b1,
                                                   const float* __restrict__ W2,
                                                   const float* __restrict__ b2) {
    extern __shared__ float sm[];
    float* sH  = sm;            // [128][68]
    float* sX  = sm + 8704;     // [64][68]
    float* sW1 = sm + 8704 + 4352;  // [64][128]
    float* sW2 = sm + 8704;     // [128][64]  (phase-2 overlay of sX+sW1)

    int tid = threadIdx.x;
    int base = blockIdx.x * 64;
    const float* h_in  = cur ? g_h1 : g_h0;
    float*       h_out = cur ? g_h0 : g_h1;

    // load W1 (8192 floats)
    {
        const float4* w4 = (const float4*)W1;
        float4* s4 = (float4*)sW1;
#pragma unroll
        for (int i = 0; i < 8; i++) s4[tid + i * 256] = w4[tid + i * 256];
    }
    // build sX[k][n] = h + agg (transposed)
    for (int idx = tid; idx < 64 * 64; idx += 256) {
        int n = idx >> 6, f = idx & 63;
        int gn = base + n;
        float v = 0.0f;
        if (gn < N_NODES)
            v = h_in[(size_t)gn * HDIM + f] + g_agg[(size_t)gn * HDIM + f];
        sX[f * SX_STRIDE + n] = v;
    }
    __syncthreads();

    int nodeg = tid & 15;   // 16 groups of 4 nodes
    int hidg  = tid >> 4;   // 16 groups of 8 hidden

    // ---- phase 1: hid = relu(x @ W1 + b1) ----
    float acc[4][8];
    {
        float4 ba = *(const float4*)&b1[hidg * 8];
        float4 bbv = *(const float4*)&b1[hidg * 8 + 4];
#pragma unroll
        for (int n = 0; n < 4; n++) {
            acc[n][0] = ba.x;  acc[n][1] = ba.y;  acc[n][2] = ba.z;  acc[n][3] = ba.w;
            acc[n][4] = bbv.x; acc[n][5] = bbv.y; acc[n][6] = bbv.z; acc[n][7] = bbv.w;
        }
    }
#pragma unroll 4
    for (int k = 0; k < 64; k++) {
        float4 xv = *(const float4*)&sX[k * SX_STRIDE + nodeg * 4];
        float4 wa = *(const float4*)&sW1[k * 128 + hidg * 8];
        float4 wb = *(const float4*)&sW1[k * 128 + hidg * 8 + 4];
        float xs[4] = { xv.x, xv.y, xv.z, xv.w };
#pragma unroll
        for (int n = 0; n < 4; n++) {
            acc[n][0] = fmaf(xs[n], wa.x, acc[n][0]);
            acc[n][1] = fmaf(xs[n], wa.y, acc[n][1]);
            acc[n][2] = fmaf(xs[n], wa.z, acc[n][2]);
            acc[n][3] = fmaf(xs[n], wa.w, acc[n][3]);
            acc[n][4] = fmaf(xs[n], wb.x, acc[n][4]);
            acc[n][5] = fmaf(xs[n], wb.y, acc[n][5]);
            acc[n][6] = fmaf(xs[n], wb.z, acc[n][6]);
            acc[n][7] = fmaf(xs[n], wb.w, acc[n][7]);
        }
    }
    // write hidden (relu) to sH[hid][node] as float4 over 4 nodes: conflict-free
#pragma unroll
    for (int hh = 0; hh < 8; hh++) {
        float4 v = make_float4(fmaxf(acc[0][hh], 0.f), fmaxf(acc[1][hh], 0.f),
                               fmaxf(acc[2][hh], 0.f), fmaxf(acc[3][hh], 0.f));
        *(float4*)&sH[(hidg * 8 + hh) * SH_STRIDE + nodeg * 4] = v;
    }
    __syncthreads();

    // load W2 into overlay region
    {
        const float4* w4 = (const float4*)W2;
        float4* s4 = (float4*)sW2;
#pragma unroll
        for (int i = 0; i < 8; i++) s4[tid + i * 256] = w4[tid + i * 256];
    }
    __syncthreads();

    // ---- phase 2: out = relu(hid @ W2 + b2) ----
    int outg = tid >> 4;   // 16 groups of 4 outputs
    float4 a2[4];
    {
        float4 bv = *(const float4*)&b2[outg * 4];
#pragma unroll
        for (int n = 0; n < 4; n++) a2[n] = bv;
    }
#pragma unroll 4
    for (int k = 0; k < 128; k++) {
        float4 hv = *(const float4*)&sH[k * SH_STRIDE + nodeg * 4];
        float4 wv = *(const float4*)&sW2[k * 64 + outg * 4];
        float hs[4] = { hv.x, hv.y, hv.z, hv.w };
#pragma unroll
        for (int n = 0; n < 4; n++) {
            a2[n].x = fmaf(hs[n], wv.x, a2[n].x);
            a2[n].y = fmaf(hs[n], wv.y, a2[n].y);
            a2[n].z = fmaf(hs[n], wv.z, a2[n].z);
            a2[n].w = fmaf(hs[n], wv.w, a2[n].w);
        }
    }
#pragma unroll
    for (int n = 0; n < 4; n++) {
        int gn = base + nodeg * 4 + n;
        if (gn < N_NODES) {
            float4 r = make_float4(fmaxf(a2[n].x, 0.f), fmaxf(a2[n].y, 0.f),
                                   fmaxf(a2[n].z, 0.f), fmaxf(a2[n].w, 0.f));
            *(float4*)&h_out[(size_t)gn * HDIM + outg * 4] = r;
        }
    }
}

// ---------------- global mean pool (accumulate) -------------------------------
__global__ void __launch_bounds__(256) pool_kernel(int cur, const int* __restrict__ batch) {
    int t = blockIdx.x * 256 + threadIdx.x;
    int n = t >> 4, g = t & 15;
    if (n >= N_NODES) return;
    const float* h = cur ? g_h1 : g_h0;
    int b = __ldg(batch + n);
    float4 hv = ((const float4*)(h + (size_t)n * HDIM))[g];
    red4(g_pool + (size_t)b * HDIM + g * 4, hv.x, hv.y, hv.z, hv.w);
    if (g == 0) atomicAdd(g_cnt + b, 1.0f);
}

// ---------------- graph head --------------------------------------------------
__global__ void __launch_bounds__(256) head_kernel(const float* __restrict__ graph_attr,
                                                   const float* __restrict__ d1W, const float* __restrict__ d1b,
                                                   const float* __restrict__ d2W, const float* __restrict__ d2b,
                                                   const float* __restrict__ oW,  const float* __restrict__ ob,
                                                   float* __restrict__ out) {
    int t = blockIdx.x * 256 + threadIdx.x;
    int g = t >> 5, lane = t & 31;
    if (g >= N_GRAPHS) return;
    float cnt = fmaxf(g_cnt[g], 1.0f);
    float p0 = g_pool[g * HDIM + lane] / cnt;
    float p1 = g_pool[g * HDIM + 32 + lane] / cnt;
    float ga = (lane < 10) ? graph_attr[g * 10 + lane] : 0.0f;

    float a = d1b[lane];
#pragma unroll
    for (int k = 0; k < 32; k++) a = fmaf(__shfl_sync(0xffffffffu, p0, k), d1W[k * 32 + lane], a);
#pragma unroll
    for (int k = 0; k < 32; k++) a = fmaf(__shfl_sync(0xffffffffu, p1, k), d1W[(32 + k) * 32 + lane], a);
#pragma unroll
    for (int k = 0; k < 10; k++) a = fmaf(__shfl_sync(0xffffffffu, ga, k), d1W[(64 + k) * 32 + lane], a);
    a = fmaxf(a, 0.0f);

    float bsum = d2b[lane];
#pragma unroll
    for (int k = 0; k < 32; k++) bsum = fmaf(__shfl_sync(0xffffffffu, a, k), d2W[k * 32 + lane], bsum);
    bsum = fmaxf(bsum, 0.0f);

    float v = bsum * oW[lane];
#pragma unroll
    for (int s = 16; s > 0; s >>= 1) v += __shfl_xor_sync(0xffffffffu, v, s);
    if (lane == 0) out[g] = 1.0f / (1.0f + expf(-(v + ob[0])));
}

// ---------------- launch -------------------------------------------------------
extern "C" void kernel_launch(void* const* d_in, const int* in_sizes, int n_in,
                              void* d_out, int out_size) {
    const float* x          = (const float*)d_in[0];
    const float* edge_attr  = (const float*)d_in[1];
    const float* graph_attr = (const float*)d_in[2];
    const int*   edge_index = (const int*)d_in[3];
    const int*   batch      = (const int*)d_in[4];
    const float* node_W     = (const float*)d_in[5];
    const float* node_b     = (const float*)d_in[6];
    const float* edge_W     = (const float*)d_in[7];
    const float* edge_b     = (const float*)d_in[8];
    const float* cW1[3] = { (const float*)d_in[9],  (const float*)d_in[13], (const float*)d_in[17] };
    const float* cb1[3] = { (const float*)d_in[10], (const float*)d_in[14], (const float*)d_in[18] };
    const float* cW2[3] = { (const float*)d_in[11], (const float*)d_in[15], (const float*)d_in[19] };
    const float* cb2[3] = { (const float*)d_in[12], (const float*)d_in[16], (const float*)d_in[20] };
    const float* d1W = (const float*)d_in[21];
    const float* d1b = (const float*)d_in[22];
    const float* d2W = (const float*)d_in[23];
    const float* d2b = (const float*)d_in[24];
    const float* oW  = (const float*)d_in[25];
    const float* ob  = (const float*)d_in[26];
    const int* esrc = edge_index;
    const int* edst = edge_index + N_EDGES;
    float* out = (float*)d_out;

    const int SMEM_MLP = SMEM_FLOATS * 4;   // 84992 bytes
    cudaFuncSetAttribute((const void*)node_mlp,
                         cudaFuncAttributeMaxDynamicSharedMemorySize, SMEM_MLP);

    zero_small<<<(N_NODES + 255) / 256, 256>>>();
    input_proj<<<(N_NODES * 16) / 256, 256>>>(x, node_W, node_b);

    // CSR build (once, reused by all 3 convs)
    hist_kernel<<<(N_EDGES + 255) / 256, 256>>>(edst);
    scan1_kernel<<<NSCAN, SCAN_BLK>>>();
    scan2_kernel<<<1, 256>>>();
    scan3_kernel<<<(N_NODES + 255) / 256, 256>>>();
    scatter_kernel<<<(N_EDGES + 255) / 256, 256>>>(edge_attr, esrc, edst);

    int cur = 0;
    for (int c = 0; c < 3; c++) {
        agg_pass<<<N_NODES / 8, 256>>>(cur, edge_W, edge_b);
        node_mlp<<<(N_NODES + 63) / 64, 256, SMEM_MLP>>>(cur, cW1[c], cb1[c], cW2[c], cb2[c]);
        cur ^= 1;
    }

    pool_kernel<<<(N_NODES * 16 + 255) / 256, 256>>>(cur, batch);
    head_kernel<<<(N_GRAPHS * 32) / 256, 256>>>(graph_attr, d1W, d1b, d2W, d2b, oW, ob, out);
}